// round 4
// baseline (speedup 1.0000x reference)
#include <cuda_runtime.h>

#define NN 50000
#define DD 128
#define EE 800000

// ---- scratch (__device__ globals: allocation-free) ----
__device__ int   g_cntrow[NN];     // degree over row (for CSR)
__device__ int   g_degcol[NN];     // degree over col (for norm)
__device__ int   g_off[NN + 1];    // CSR row offsets
__device__ int   g_cursor[NN];     // scatter cursors
__device__ int2  g_edge[EE];       // row-sorted edges: (col, bits(dis[col]))
__device__ float g_dis[NN];        // deg_col^-0.5 (0 if deg==0)
__device__ unsigned int g_maxbits; // ordered-float max; zero-init == -inf encoding,
                                   // atomicMax idempotent across graph replays
__device__ float2 g_ppM;           // (pp, M = pp*max(x))

__device__ __forceinline__ unsigned int ford(float f) {
    unsigned int b = __float_as_uint(f);
    return (b & 0x80000000u) ? ~b : (b | 0x80000000u);
}
__device__ __forceinline__ float funord(unsigned int u) {
    unsigned int b = (u & 0x80000000u) ? (u & 0x7FFFFFFFu) : ~u;
    return __uint_as_float(b);
}

// L1: zero counters AND global max of x
__global__ void k_zero_max(const float* __restrict__ x) {
    const int gsz = gridDim.x * blockDim.x;
    int gi = blockIdx.x * blockDim.x + threadIdx.x;
    for (int i = gi; i < NN; i += gsz) { g_cntrow[i] = 0; g_degcol[i] = 0; }

    float m = -3.402823466e38f;
    const float4* x4 = (const float4*)x;
    const int n4 = (NN * DD) / 4;
    for (int i = gi; i < n4; i += gsz) {
        float4 v = x4[i];
        m = fmaxf(m, fmaxf(fmaxf(v.x, v.y), fmaxf(v.z, v.w)));
    }
#pragma unroll
    for (int o = 16; o; o >>= 1) m = fmaxf(m, __shfl_xor_sync(~0u, m, o));
    __shared__ float sm[32];
    int lane = threadIdx.x & 31, w = threadIdx.x >> 5;
    if (lane == 0) sm[w] = m;
    __syncthreads();
    if (w == 0) {
        m = (lane < (int)(blockDim.x >> 5)) ? sm[lane] : -3.402823466e38f;
#pragma unroll
        for (int o = 16; o; o >>= 1) m = fmaxf(m, __shfl_xor_sync(~0u, m, o));
        if (lane == 0) atomicMax(&g_maxbits, ford(m));
    }
}

// L2: histogram degrees, 4 edges/thread for MLP
__global__ void k_count(const int* __restrict__ ei) {
    int t = blockIdx.x * blockDim.x + threadIdx.x;
    if (t * 4 >= EE) return;
    int4 r4 = ((const int4*)ei)[t];
    int4 c4 = ((const int4*)(ei + EE))[t];
    atomicAdd(&g_cntrow[r4.x], 1); atomicAdd(&g_degcol[c4.x], 1);
    atomicAdd(&g_cntrow[r4.y], 1); atomicAdd(&g_degcol[c4.y], 1);
    atomicAdd(&g_cntrow[r4.z], 1); atomicAdd(&g_degcol[c4.z], 1);
    atomicAdd(&g_cntrow[r4.w], 1); atomicAdd(&g_degcol[c4.w], 1);
}

// L3: single-block scan of cntrow -> off/cursor, plus dis[] and ppM
__global__ void k_scan_dis(const float* __restrict__ p) {
    const int C = (NN + 1023) / 1024;  // 49 per thread
    __shared__ int part[1024];
    int tid = threadIdx.x;
    int base = tid * C;
    int s = 0;
    for (int k = 0; k < C; k++) {
        int i = base + k;
        s += (i < NN) ? g_cntrow[i] : 0;
    }
    part[tid] = s;
    __syncthreads();
    for (int off = 1; off < 1024; off <<= 1) {
        int t = (tid >= off) ? part[tid - off] : 0;
        __syncthreads();
        part[tid] += t;
        __syncthreads();
    }
    int run = part[tid] - s;  // exclusive prefix of chunk
    for (int k = 0; k < C; k++) {
        int i = base + k;
        if (i < NN) {
            g_off[i] = run;
            g_cursor[i] = run;
            run += g_cntrow[i];
            int dg = g_degcol[i];
            g_dis[i] = (dg > 0) ? rsqrtf((float)dg) : 0.0f;
        }
    }
    if (tid == 1023) g_off[NN] = run;
    if (tid == 0) {
        float pp = 2.0f / (1.0f + __expf(-p[0]));
        g_ppM = make_float2(pp, pp * funord(g_maxbits));
    }
}

// L4: scatter (col, dis[col]) into row-sorted order, 4 edges/thread
__global__ void k_scatter(const int* __restrict__ ei) {
    int t = blockIdx.x * blockDim.x + threadIdx.x;
    if (t * 4 >= EE) return;
    int4 r4 = ((const int4*)ei)[t];
    int4 c4 = ((const int4*)(ei + EE))[t];
    int p0 = atomicAdd(&g_cursor[r4.x], 1);
    int p1 = atomicAdd(&g_cursor[r4.y], 1);
    int p2 = atomicAdd(&g_cursor[r4.z], 1);
    int p3 = atomicAdd(&g_cursor[r4.w], 1);
    float w0 = g_dis[c4.x], w1 = g_dis[c4.y], w2 = g_dis[c4.z], w3 = g_dis[c4.w];
    g_edge[p0] = make_int2(c4.x, __float_as_int(w0));
    g_edge[p1] = make_int2(c4.y, __float_as_int(w1));
    g_edge[p2] = make_int2(c4.z, __float_as_int(w2));
    g_edge[p3] = make_int2(c4.w, __float_as_int(w3));
}

// L5: block (128 threads) per node; thread d owns feature d; edge loop unroll 8
__global__ void __launch_bounds__(128) k_main(const float* __restrict__ x,
                                              const float* __restrict__ eps,
                                              float* __restrict__ out) {
    const int r = blockIdx.x;
    const int d = threadIdx.x;
    const int start = g_off[r];
    const int end   = g_off[r + 1];
    const float2 ppM = g_ppM;
    const float pp = ppM.x, M = ppM.y;

    __shared__ int2 s_e[128];

    float num = 0.0f, den = 0.0f;

#define EDGE(t, wk)                                      \
    {                                                    \
        float sv = __expf(fmaf(pp, (t), -(M)));          \
        den = fmaf(sv, (wk), den);                       \
        num = fmaf(sv * (t), (wk), num);                 \
    }

    for (int base = start; base < end; base += 128) {
        int j = base + d;
        if (j < end) s_e[d] = g_edge[j];
        __syncthreads();
        int m = end - base;
        if (m > 128) m = 128;
        int k = 0;
        for (; k + 8 <= m; k += 8) {
            int2 e0 = s_e[k],     e1 = s_e[k + 1], e2 = s_e[k + 2], e3 = s_e[k + 3];
            int2 e4 = s_e[k + 4], e5 = s_e[k + 5], e6 = s_e[k + 6], e7 = s_e[k + 7];
            float t0 = __ldg(&x[e0.x * DD + d]);
            float t1 = __ldg(&x[e1.x * DD + d]);
            float t2 = __ldg(&x[e2.x * DD + d]);
            float t3 = __ldg(&x[e3.x * DD + d]);
            float t4 = __ldg(&x[e4.x * DD + d]);
            float t5 = __ldg(&x[e5.x * DD + d]);
            float t6 = __ldg(&x[e6.x * DD + d]);
            float t7 = __ldg(&x[e7.x * DD + d]);
            EDGE(t0, __int_as_float(e0.y)) EDGE(t1, __int_as_float(e1.y))
            EDGE(t2, __int_as_float(e2.y)) EDGE(t3, __int_as_float(e3.y))
            EDGE(t4, __int_as_float(e4.y)) EDGE(t5, __int_as_float(e5.y))
            EDGE(t6, __int_as_float(e6.y)) EDGE(t7, __int_as_float(e7.y))
        }
        for (; k < m; k++) {
            int2 e = s_e[k];
            float t = __ldg(&x[e.x * DD + d]);
            EDGE(t, __int_as_float(e.y))
        }
        __syncthreads();
    }
#undef EDGE

    float dr = g_dis[r];
    float xv = x[r * DD + d];
    float o = __fdividef(dr * num, fmaf(dr, den, 1e-6f)) + (1.0f + eps[0]) * xv;
    out[r * DD + d] = o;
}

extern "C" void kernel_launch(void* const* d_in, const int* in_sizes, int n_in,
                              void* d_out, int out_size) {
    const float* x   = (const float*)d_in[0];
    const int*   ei  = (const int*)d_in[1];
    const float* eps = (const float*)d_in[2];
    const float* p   = (const float*)d_in[3];
    float* out = (float*)d_out;

    k_zero_max<<<512, 256>>>(x);
    k_count   <<<(EE / 4 + 255) / 256, 256>>>(ei);
    k_scan_dis<<<1, 1024>>>(p);
    k_scatter <<<(EE / 4 + 255) / 256, 256>>>(ei);
    k_main    <<<NN, 128>>>(x, eps, out);
}